// round 1
// baseline (speedup 1.0000x reference)
#include <cuda_runtime.h>

#define TS       100
#define FDIM     64
#define HDIM     32
#define ESTRIDE  66            // row stride in floats: 66 -> (2t+k) bank pattern, float2-aligned
#define NTHREADS 256
#define NPAIR    (TS * (TS - 1) / 2)      // 4950
#define DEEP_N   (TS * HDIM)              // 3200
#define WIDE_OFF (DEEP_N + NPAIR)         // 8150
#define NBLK     25                       // 100 / 4 row-blocks
#define NTRI_BLK (NBLK * (NBLK + 1) / 2)  // 325 upper-tri block pairs (incl diagonal blocks)
#define NTASKS   (NTRI_BLK * 2)           // split each block over 2 k-halves -> 650

// ---------------- packed f32x2 helpers (Blackwell FFMA2 pipe) ----------------
__device__ __forceinline__ unsigned long long pack2(float lo, float hi) {
    unsigned long long r;
    asm("mov.b64 %0, {%1, %2};" : "=l"(r) : "f"(lo), "f"(hi));
    return r;
}
__device__ __forceinline__ unsigned long long splat2(float x) {
    unsigned long long r;
    asm("mov.b64 %0, {%1, %1};" : "=l"(r) : "f"(x));
    return r;
}
__device__ __forceinline__ void fma2(unsigned long long& d, unsigned long long a,
                                     unsigned long long b) {
    asm("fma.rn.f32x2 %0, %1, %2, %3;" : "=l"(d) : "l"(a), "l"(b), "l"(d));
}
__device__ __forceinline__ float hsum2(unsigned long long v) {
    float lo, hi;
    asm("mov.b64 {%0, %1}, %2;" : "=f"(lo), "=f"(hi) : "l"(v));
    return lo + hi;
}
__device__ __forceinline__ void unpack2(unsigned long long v, float& lo, float& hi) {
    asm("mov.b64 {%0, %1}, %2;" : "=f"(lo), "=f"(hi) : "l"(v));
}

__global__ __launch_bounds__(NTHREADS)
void deepfm_fused_kernel(const int* __restrict__ x,
                         const float* __restrict__ emb,
                         const float* __restrict__ w_deep,
                         const float* __restrict__ b_deep,
                         const float* __restrict__ w_ffn,
                         const float* __restrict__ b_ffn,
                         float* __restrict__ out)
{
    __shared__ __align__(16) float es[TS * ESTRIDE];   // 26.4 KB embedding tile
    __shared__ __align__(16) float wd[FDIM * HDIM];    // 8 KB deep weights
    __shared__ int   tok[TS];
    __shared__ float red[NTHREADS / 32];

    const int b   = blockIdx.x;
    const int tid = threadIdx.x;

    // ---- phase 0: tokens + w_deep into shared ----
    if (tid < TS) tok[tid] = x[b * TS + tid];
    for (int i = tid; i < (FDIM * HDIM) / 4; i += NTHREADS)
        ((float4*)wd)[i] = ((const float4*)w_deep)[i];
    __syncthreads();

    // ---- phase 1: gather e = emb[x[b]] into shared (float2 granularity) ----
    for (int idx = tid; idx < TS * (FDIM / 2); idx += NTHREADS) {
        const int row = idx >> 5;            // /32 float2 per row
        const int c   = idx & 31;
        const float2 v = *(const float2*)(emb + (long)tok[row] * FDIM + c * 2);
        *(float2*)(es + row * ESTRIDE + c * 2) = v;
    }
    __syncthreads();

    float acc = 0.f;

    // ---- wide term: sum e[t,f] * w_ffn[WIDE_OFF + t*64 + f] ----
    {
        const float* ww = w_ffn + WIDE_OFF;
        for (int idx = tid; idx < TS * FDIM; idx += NTHREADS) {
            const int t = idx >> 6, f = idx & 63;
            acc += es[t * ESTRIDE + f] * ww[idx];
        }
    }

    // ---- deep term: 25 t-blocks x 8 h-blocks = 200 tasks (threads 0..199) ----
    if (tid < NBLK * 8) {
        const int t0 = (tid >> 3) * 4;
        const int h0 = (tid & 7) * 4;
        unsigned long long a01[4] = {0, 0, 0, 0};
        unsigned long long a23[4] = {0, 0, 0, 0};
        #pragma unroll 4
        for (int k = 0; k < FDIM; ++k) {
            const float4 w4 = *(const float4*)(wd + k * HDIM + h0);
            const unsigned long long w01 = pack2(w4.x, w4.y);
            const unsigned long long w23 = pack2(w4.z, w4.w);
            #pragma unroll
            for (int i = 0; i < 4; ++i) {
                const unsigned long long ei = splat2(es[(t0 + i) * ESTRIDE + k]);
                fma2(a01[i], ei, w01);
                fma2(a23[i], ei, w23);
            }
        }
        const float4 bd = *(const float4*)(b_deep + h0);
        #pragma unroll
        for (int i = 0; i < 4; ++i) {
            float d0, d1, d2, d3;
            unpack2(a01[i], d0, d1);
            unpack2(a23[i], d2, d3);
            const float* wdf = w_ffn + (t0 + i) * HDIM + h0;
            acc += fmaxf(d0 + bd.x, 0.f) * wdf[0];
            acc += fmaxf(d1 + bd.y, 0.f) * wdf[1];
            acc += fmaxf(d2 + bd.z, 0.f) * wdf[2];
            acc += fmaxf(d3 + bd.w, 0.f) * wdf[3];
        }
    }

    // ---- fm term: upper-tri 4x4 pair blocks, each split into 2 k-halves ----
    {
        const float* wfm = w_ffn + DEEP_N;
        for (int task = tid; task < NTASKS; task += NTHREADS) {
            const int blk = task >> 1;
            const int k0  = (task & 1) * (FDIM / 2);
            // map blk -> (ib, jb) with ib <= jb over 25x25 upper triangle
            int ib = 0, rem = blk;
            while (rem >= NBLK - ib) { rem -= NBLK - ib; ++ib; }
            const int jb = ib + rem;
            const int i0 = ib * 4, j0 = jb * 4;

            unsigned long long pacc[16];
            #pragma unroll
            for (int p = 0; p < 16; ++p) pacc[p] = 0ull;

            #pragma unroll 4
            for (int k = k0; k < k0 + FDIM / 2; k += 2) {
                unsigned long long ai[4], aj[4];
                #pragma unroll
                for (int i = 0; i < 4; ++i)
                    ai[i] = *(const unsigned long long*)(es + (i0 + i) * ESTRIDE + k);
                #pragma unroll
                for (int j = 0; j < 4; ++j)
                    aj[j] = *(const unsigned long long*)(es + (j0 + j) * ESTRIDE + k);
                #pragma unroll
                for (int i = 0; i < 4; ++i)
                    #pragma unroll
                    for (int j = 0; j < 4; ++j)
                        fma2(pacc[i * 4 + j], ai[i], aj[j]);
            }

            #pragma unroll
            for (int i = 0; i < 4; ++i) {
                const int gi = i0 + i;
                #pragma unroll
                for (int j = 0; j < 4; ++j) {
                    const int gj = j0 + j;
                    if (gi < gj) {
                        const int idx = gi * (2 * TS - gi - 1) / 2 + (gj - gi - 1);
                        acc += hsum2(pacc[i * 4 + j]) * wfm[idx];
                    }
                }
            }
        }
    }

    // ---- block reduce + sigmoid ----
    #pragma unroll
    for (int off = 16; off; off >>= 1)
        acc += __shfl_xor_sync(0xffffffffu, acc, off);
    if ((tid & 31) == 0) red[tid >> 5] = acc;
    __syncthreads();
    if (tid == 0) {
        float total = 0.f;
        #pragma unroll
        for (int w = 0; w < NTHREADS / 32; ++w) total += red[w];
        total += b_ffn[0];
        out[b] = 1.f / (1.f + expf(-total));
    }
}

extern "C" void kernel_launch(void* const* d_in, const int* in_sizes, int n_in,
                              void* d_out, int out_size) {
    const int*   x      = (const int*)d_in[0];
    const float* emb    = (const float*)d_in[1];
    const float* w_deep = (const float*)d_in[2];
    const float* b_deep = (const float*)d_in[3];
    const float* w_ffn  = (const float*)d_in[4];
    const float* b_ffn  = (const float*)d_in[5];
    float* out = (float*)d_out;

    deepfm_fused_kernel<<<8192, NTHREADS>>>(x, emb, w_deep, b_deep, w_ffn, b_ffn, out);
}